// round 14
// baseline (speedup 1.0000x reference)
#include <cuda_runtime.h>
#include <cstddef>
#include <cstdint>

#define IMGS 1280

__device__ float g_pool1[IMGS * 3 * 37 * 37];   // 21 MB scratch (L2-hot)
__device__ float g_nf[IMGS * 6];
__device__ float g_sink;                        // DCE-blocker for L2 warmup

// ---------------------------------------------------------------------------
// Stage 1+2 fused: conv1(3->3,k3,s2)+maxpool3+relu via cp.async double-
// buffered pipeline (19 groups of 2 pooled rows), then inline conv2+maxpool3
// +relu+36->6 linear epilogue reading the block's own pooled map back from L2.
// Grid = 1280 (one image/block), 128 threads, 3 blocks/SM.
// ---------------------------------------------------------------------------
#define CHUNK_F   8736
#define S1_SMEM_FLOATS (2 * CHUNK_F + 160)
#define S1_SMEM_BYTES  (S1_SMEM_FLOATS * 4)

__device__ __forceinline__ void cp_async16(uint32_t saddr, const void* gptr) {
    asm volatile("cp.async.cg.shared.global [%0], [%1], 16;\n"
                 :: "r"(saddr), "l"(gptr));
}

__global__ __launch_bounds__(128, 3) void stage12_kernel(
    const float* __restrict__ nodes,
    const float* __restrict__ w1g,   // [oc][ci][3][3]
    const float* __restrict__ b1g,   // [3]
    const float* __restrict__ w2g,   // [1][3][3][3]
    const float* __restrict__ b2g,   // [1]
    const float* __restrict__ linw,  // [6][36]
    const float* __restrict__ linb,  // [6]
    const float* __restrict__ fc1w,  // L2-warmed for stage3
    const float* __restrict__ fc2w)
{
    extern __shared__ float sm[];
    float* w1s = sm + 2 * CHUNK_F;      // [ci][oc][kh][kw] (81)
    float* bsh = w1s + 81;              // [3]
    float* s2  = bsh + 4;               // [36] epilogue pooled cells

    const int tid = threadIdx.x;
    const int img = blockIdx.x;

    if (tid < 81) {
        int oc = tid / 27, rem = tid - oc * 27;
        int ci = rem / 9,  k   = rem - ci * 9;
        w1s[ci * 27 + oc * 9 + k] = w1g[tid];
    }
    if (tid < 3) bsh[tid] = b1g[tid];

    const float* src = nodes + (size_t)img * 150528;
    const uint32_t s_base = (uint32_t)__cvta_generic_to_shared(sm);

    auto load_group = [&](int g) {
        const int r0   = 12 * g;
        const int cnt  = (g == 18) ? 7 : 13;          // input rows
        const int n4   = cnt * 56;                     // float4 per channel
        const uint32_t dbase = s_base + ((g & 1) * CHUNK_F) * 4;
#pragma unroll 1
        for (int ci = 0; ci < 3; ci++) {
            const float* gsrc = src + ci * 50176 + r0 * 224;
            const uint32_t dch = dbase + ci * (2912 * 4);
            for (int i = tid; i < n4; i += 128)
                cp_async16(dch + i * 16, gsrc + i * 4);
        }
        asm volatile("cp.async.commit_group;\n" ::: "memory");
    };

    load_group(0);

#pragma unroll 1
    for (int g = 0; g < 19; g++) {
        if (g + 1 < 19) {
            load_group(g + 1);
            asm volatile("cp.async.wait_group 1;\n" ::: "memory");
        } else {
            asm volatile("cp.async.wait_group 0;\n" ::: "memory");
        }
        __syncthreads();

        const int p_base = 2 * g;
        const int nrows  = (g == 18) ? 1 : 2;
        const int cells  = nrows * 37;
        const float* buf = sm + (g & 1) * CHUNK_F;

        if (tid < cells) {
            const int pl = tid / 37;
            const int q  = tid - pl * 37;

            float acc[3][3][3];   // [oc][pr][pc]
#pragma unroll
            for (int oc = 0; oc < 3; oc++)
#pragma unroll
                for (int pr = 0; pr < 3; pr++)
#pragma unroll
                    for (int pc = 0; pc < 3; pc++) acc[oc][pr][pc] = 0.f;

#pragma unroll
            for (int ci = 0; ci < 3; ci++) {
                float wl[27];
#pragma unroll
                for (int j = 0; j < 27; j++) wl[j] = w1s[ci * 27 + j];

                const float* base = buf + ci * 2912 + (6 * pl) * 224 + 6 * q;
#pragma unroll
                for (int r = 0; r < 7; r++) {
                    const float2* rp = (const float2*)(base + r * 224);
                    float2 a0 = rp[0], a1 = rp[1], a2 = rp[2], a3 = rp[3];
                    float v[7] = {a0.x, a0.y, a1.x, a1.y, a2.x, a2.y, a3.x};
#pragma unroll
                    for (int pr = 0; pr < 3; pr++) {
                        const int kh = r - 2 * pr;
                        if (kh >= 0 && kh < 3) {
#pragma unroll
                            for (int oc = 0; oc < 3; oc++)
#pragma unroll
                                for (int pc = 0; pc < 3; pc++)
#pragma unroll
                                    for (int kw = 0; kw < 3; kw++)
                                        acc[oc][pr][pc] =
                                            fmaf(v[2 * pc + kw],
                                                 wl[oc * 9 + kh * 3 + kw],
                                                 acc[oc][pr][pc]);
                        }
                    }
                }
            }

            const int p = p_base + pl;
            const size_t ob = (size_t)img * 4107 + (size_t)p * 37 + q;
#pragma unroll
            for (int oc = 0; oc < 3; oc++) {
                float m = acc[oc][0][0];
#pragma unroll
                for (int pr = 0; pr < 3; pr++)
#pragma unroll
                    for (int pc = 0; pc < 3; pc++) m = fmaxf(m, acc[oc][pr][pc]);
                g_pool1[ob + oc * 1369] = fmaxf(m + bsh[oc], 0.f);
            }
        }
        __syncthreads();   // protect buf[g&1] before group g+2 overwrites it
    }

    // ================= inline stage-2 epilogue =================
    // Block's own g_pool1 writes are visible after the final __syncthreads.
    // Buffers are free now; stage the 4107-float pooled map into buffer A.
    float* s = sm;
    const float* srcp = g_pool1 + (size_t)img * 4107;
    for (int i = tid; i < 4107; i += 128) s[i] = srcp[i];

    // L2 warm-up of stage3 weights from the LAST-scheduled block
    if (img == IMGS - 1) {
        float acc = 0.f;
        const float4* p1 = (const float4*)fc1w;
        for (int i = tid; i < 7200; i += 128) {
            float4 v = p1[i]; acc += v.x + v.y + v.z + v.w;
        }
        const float4* p2 = (const float4*)fc2w;
        for (int i = tid; i < 1800; i += 128) {
            float4 v = p2[i]; acc += v.x + v.y + v.z + v.w;
        }
        if (acc == -1.2345678e33f) g_sink = acc;   // never true; keeps loads live
    }
    __syncthreads();

    if (tid < 36) {
        const int pr = tid / 6, pc = tid - 6 * pr;
        const float bias = b2g[0];
        float w[27];
#pragma unroll
        for (int i = 0; i < 27; i++) w[i] = w2g[i];
        float pool = -1e30f;
#pragma unroll
        for (int r = 0; r < 3; r++) {
#pragma unroll
            for (int c = 0; c < 3; c++) {
                const int R = 3 * pr + r;
                const int C = 3 * pc + c;
                float a = bias;
#pragma unroll
                for (int ci = 0; ci < 3; ci++)
#pragma unroll
                    for (int kh = 0; kh < 3; kh++)
#pragma unroll
                        for (int kw = 0; kw < 3; kw++)
                            a = fmaf(s[ci * 1369 + (2 * R + kh) * 37 + 2 * C + kw],
                                     w[ci * 9 + kh * 3 + kw], a);
                pool = fmaxf(pool, a);
            }
        }
        s2[tid] = fmaxf(pool, 0.f);
    }
    __syncthreads();

    if (tid < 6) {
        float a = linb[tid];
#pragma unroll
        for (int k = 0; k < 36; k++) a = fmaf(s2[k], linw[tid * 36 + k], a);
        g_nf[img * 6 + tid] = a;
    }
}

// ---------------------------------------------------------------------------
// Stage 3: message passing + MLP head. One block per node, 256 threads.
// Split-K across thread pairs (tid, tid+128) with float4 loads.
// ---------------------------------------------------------------------------
__global__ __launch_bounds__(256) void stage3_kernel(
    const float* __restrict__ pos,     // [64,5,4,6]
    const float* __restrict__ attmap,  // [64,5,4,4]
    const float* __restrict__ framew, const float* __restrict__ frameb,
    const float* __restrict__ lastw,  const float* __restrict__ lastb,
    const float* __restrict__ fc1w,   const float* __restrict__ fc1b,
    const float* __restrict__ fc2w,   const float* __restrict__ fc2b,
    const float* __restrict__ fc3w,   const float* __restrict__ fc3b,
    float* __restrict__ out)
{
    const int n   = blockIdx.x;
    const int tid = threadIdx.x;
    const int half = tid >> 7;        // 0 or 1
    const int o    = tid & 127;

    __shared__ __align__(16) float feat[240];
    __shared__ __align__(16) float h1[120];
    __shared__ __align__(16) float h2[60];
    __shared__ float part1[240];
    __shared__ float part2[120];
    __shared__ float part3[12];

    const float* posn = pos + n * 120;

    if (tid < 120) {
        const int f  = tid / 24;
        const int nn = (tid / 6) % 4;
        const int d  = tid % 6;
        const float* att = attmap + n * 80 + f * 16;

        feat[f * 48 + nn * 12 + d] = g_nf[(n * 20 + f * 4 + nn) * 6 + d];

        float acc = 0.f;
        const float fb = frameb[d];
#pragma unroll
        for (int j = 0; j < 4; j++) {
            float m = fb;
#pragma unroll
            for (int e = 0; e < 6; e++)
                m = fmaf(posn[(f * 4 + j) * 6 + e], framew[d * 6 + e], m);
            acc = fmaf(att[j * 4 + nn], m, acc);
        }
        if (f >= 1) {
            float l = lastb[d];
#pragma unroll
            for (int e = 0; e < 6; e++)
                l = fmaf(posn[((f - 1) * 4 + nn) * 6 + e], lastw[d * 6 + e], l);
            acc += l;
        }
        feat[f * 48 + nn * 12 + 6 + d] = acc;
    }
    __syncthreads();

    if (o < 120) {
        const float4* wr = (const float4*)(fc1w + o * 240 + half * 120);
        const float4* fe = (const float4*)feat + half * 30;
        float acc = 0.f;
#pragma unroll
        for (int k = 0; k < 30; k++) {
            float4 w4 = wr[k], f4 = fe[k];
            acc = fmaf(f4.x, w4.x, acc);
            acc = fmaf(f4.y, w4.y, acc);
            acc = fmaf(f4.z, w4.z, acc);
            acc = fmaf(f4.w, w4.w, acc);
        }
        part1[half * 120 + o] = acc;
    }
    __syncthreads();
    if (tid < 120) h1[tid] = fmaxf(part1[tid] + part1[120 + tid] + fc1b[tid], 0.f);
    __syncthreads();

    if (o < 60) {
        const float4* wr = (const float4*)(fc2w + o * 120 + half * 60);
        const float4* hh = (const float4*)h1 + half * 15;
        float acc = 0.f;
#pragma unroll
        for (int k = 0; k < 15; k++) {
            float4 w4 = wr[k], f4 = hh[k];
            acc = fmaf(f4.x, w4.x, acc);
            acc = fmaf(f4.y, w4.y, acc);
            acc = fmaf(f4.z, w4.z, acc);
            acc = fmaf(f4.w, w4.w, acc);
        }
        part2[half * 60 + o] = acc;
    }
    __syncthreads();
    if (tid < 60) h2[tid] = fmaxf(part2[tid] + part2[60 + tid] + fc2b[tid], 0.f);
    __syncthreads();

    if (o < 6) {
        const float2* wr = (const float2*)(fc3w + o * 60 + half * 30);
        const float2* hh = (const float2*)h2 + half * 15;
        float acc = 0.f;
#pragma unroll
        for (int k = 0; k < 15; k++) {
            float2 w2 = wr[k], f2 = hh[k];
            acc = fmaf(f2.x, w2.x, acc);
            acc = fmaf(f2.y, w2.y, acc);
        }
        part3[half * 6 + o] = acc;
    }
    __syncthreads();
    if (tid < 6) out[n * 6 + tid] = part3[tid] + part3[6 + tid] + fc3b[tid];
}

// ---------------------------------------------------------------------------
extern "C" void kernel_launch(void* const* d_in, const int* in_sizes, int n_in,
                              void* d_out, int out_size)
{
    const float* nodes  = (const float*)d_in[0];
    const float* pos    = (const float*)d_in[1];
    const float* attmap = (const float*)d_in[2];
    // d_in[3] = depths (unused)
    const float* conv1w = (const float*)d_in[4];
    const float* conv1b = (const float*)d_in[5];
    const float* conv2w = (const float*)d_in[6];
    const float* conv2b = (const float*)d_in[7];
    const float* linw   = (const float*)d_in[8];
    const float* linb   = (const float*)d_in[9];
    const float* framew = (const float*)d_in[10];
    const float* frameb = (const float*)d_in[11];
    const float* lastw  = (const float*)d_in[12];
    const float* lastb  = (const float*)d_in[13];
    const float* fc1w   = (const float*)d_in[14];
    const float* fc1b   = (const float*)d_in[15];
    const float* fc2w   = (const float*)d_in[16];
    const float* fc2b   = (const float*)d_in[17];
    const float* fc3w   = (const float*)d_in[18];
    const float* fc3b   = (const float*)d_in[19];

    cudaFuncSetAttribute(stage12_kernel,
                         cudaFuncAttributeMaxDynamicSharedMemorySize, S1_SMEM_BYTES);

    stage12_kernel<<<IMGS, 128, S1_SMEM_BYTES>>>(nodes, conv1w, conv1b,
                                                 conv2w, conv2b, linw, linb,
                                                 fc1w, fc2w);
    stage3_kernel<<<64, 256>>>(pos, attmap, framew, frameb, lastw, lastb,
                               fc1w, fc1b, fc2w, fc2b, fc3w, fc3b,
                               (float*)d_out);
}

// round 15
// speedup vs baseline: 1.6023x; 1.6023x over previous
#include <cuda_runtime.h>
#include <cstddef>
#include <cstdint>

#define IMGS 1280

__device__ float g_pool1[IMGS * 3 * 37 * 37];   // 21 MB scratch (L2-hot)
__device__ float g_nf[IMGS * 6];
__device__ float g_sink;                        // DCE-blocker for warmup
__device__ int   g_done;                        // stage2 completion counter

// ---------------------------------------------------------------------------
// Stage 1: conv1(3->3,k3,s2) + maxpool3 + relu via cp.async double-buffered
// smem pipeline. Grid = 1280 (one image/block), 128 threads, 3 blocks/SM.
// PROVEN 133.7us body — do not touch.
// ---------------------------------------------------------------------------
#define CHUNK_F   8736
#define S1_SMEM_FLOATS (2 * CHUNK_F + 96)
#define S1_SMEM_BYTES  (S1_SMEM_FLOATS * 4)

__device__ __forceinline__ void cp_async16(uint32_t saddr, const void* gptr) {
    asm volatile("cp.async.cg.shared.global [%0], [%1], 16;\n"
                 :: "r"(saddr), "l"(gptr));
}

__global__ __launch_bounds__(128, 3) void stage1_kernel(
    const float* __restrict__ nodes,
    const float* __restrict__ w1g,     // [oc][ci][3][3]
    const float* __restrict__ b1g)     // [3]
{
    extern __shared__ float sm[];
    float* w1s = sm + 2 * CHUNK_F;      // [ci][oc][kh][kw] (81)
    float* bsh = w1s + 81;              // [3]

    const int tid = threadIdx.x;
    const int img = blockIdx.x;

    if (img == 0 && tid == 0) g_done = 0;   // reset counter for stage23

    if (tid < 81) {
        int oc = tid / 27, rem = tid - oc * 27;
        int ci = rem / 9,  k   = rem - ci * 9;
        w1s[ci * 27 + oc * 9 + k] = w1g[tid];
    }
    if (tid < 3) bsh[tid] = b1g[tid];

    const float* src = nodes + (size_t)img * 150528;
    const uint32_t s_base = (uint32_t)__cvta_generic_to_shared(sm);

    auto load_group = [&](int g) {
        const int r0   = 12 * g;
        const int cnt  = (g == 18) ? 7 : 13;          // input rows
        const int n4   = cnt * 56;                     // float4 per channel
        const uint32_t dbase = s_base + ((g & 1) * CHUNK_F) * 4;
#pragma unroll 1
        for (int ci = 0; ci < 3; ci++) {
            const float* gsrc = src + ci * 50176 + r0 * 224;
            const uint32_t dch = dbase + ci * (2912 * 4);
            for (int i = tid; i < n4; i += 128)
                cp_async16(dch + i * 16, gsrc + i * 4);
        }
        asm volatile("cp.async.commit_group;\n" ::: "memory");
    };

    load_group(0);

#pragma unroll 1
    for (int g = 0; g < 19; g++) {
        if (g + 1 < 19) {
            load_group(g + 1);
            asm volatile("cp.async.wait_group 1;\n" ::: "memory");
        } else {
            asm volatile("cp.async.wait_group 0;\n" ::: "memory");
        }
        __syncthreads();

        const int p_base = 2 * g;
        const int nrows  = (g == 18) ? 1 : 2;
        const int cells  = nrows * 37;
        const float* buf = sm + (g & 1) * CHUNK_F;

        if (tid < cells) {
            const int pl = tid / 37;
            const int q  = tid - pl * 37;

            float acc[3][3][3];   // [oc][pr][pc]
#pragma unroll
            for (int oc = 0; oc < 3; oc++)
#pragma unroll
                for (int pr = 0; pr < 3; pr++)
#pragma unroll
                    for (int pc = 0; pc < 3; pc++) acc[oc][pr][pc] = 0.f;

#pragma unroll
            for (int ci = 0; ci < 3; ci++) {
                float wl[27];
#pragma unroll
                for (int j = 0; j < 27; j++) wl[j] = w1s[ci * 27 + j];

                const float* base = buf + ci * 2912 + (6 * pl) * 224 + 6 * q;
#pragma unroll
                for (int r = 0; r < 7; r++) {
                    const float2* rp = (const float2*)(base + r * 224);
                    float2 a0 = rp[0], a1 = rp[1], a2 = rp[2], a3 = rp[3];
                    float v[7] = {a0.x, a0.y, a1.x, a1.y, a2.x, a2.y, a3.x};
#pragma unroll
                    for (int pr = 0; pr < 3; pr++) {
                        const int kh = r - 2 * pr;
                        if (kh >= 0 && kh < 3) {
#pragma unroll
                            for (int oc = 0; oc < 3; oc++)
#pragma unroll
                                for (int pc = 0; pc < 3; pc++)
#pragma unroll
                                    for (int kw = 0; kw < 3; kw++)
                                        acc[oc][pr][pc] =
                                            fmaf(v[2 * pc + kw],
                                                 wl[oc * 9 + kh * 3 + kw],
                                                 acc[oc][pr][pc]);
                        }
                    }
                }
            }

            const int p = p_base + pl;
            const size_t ob = (size_t)img * 4107 + (size_t)p * 37 + q;
#pragma unroll
            for (int oc = 0; oc < 3; oc++) {
                float m = acc[oc][0][0];
#pragma unroll
                for (int pr = 0; pr < 3; pr++)
#pragma unroll
                    for (int pc = 0; pc < 3; pc++) m = fmaxf(m, acc[oc][pr][pc]);
                g_pool1[ob + oc * 1369] = fmaxf(m + bsh[oc], 0.f);
            }
        }
        __syncthreads();   // protect buf[g&1] before group g+2 overwrites it
    }
}

// ---------------------------------------------------------------------------
// Stage 2+3 fused: grid = 1344 x 128 threads.
//   blocks [0,1280): stage2 for image blockIdx.x -> g_nf, then signal g_done.
//   blocks [1280,1344): stage3 for node blockIdx.x-1280: do g_nf-independent
//   work + L2 weight warmup, spin on g_done==1280, then finish the MLP head.
// All 1344 blocks co-resident (smem-bound 13 blocks/SM), so the spin is safe.
// ---------------------------------------------------------------------------
__global__ __launch_bounds__(128) void stage23_kernel(
    const float* __restrict__ w2g,    const float* __restrict__ b2g,
    const float* __restrict__ linw,   const float* __restrict__ linb,
    const float* __restrict__ pos,    const float* __restrict__ attmap,
    const float* __restrict__ framew, const float* __restrict__ frameb,
    const float* __restrict__ lastw,  const float* __restrict__ lastb,
    const float* __restrict__ fc1w,   const float* __restrict__ fc1b,
    const float* __restrict__ fc2w,   const float* __restrict__ fc2b,
    const float* __restrict__ fc3w,   const float* __restrict__ fc3b,
    float* __restrict__ out)
{
    const int tid = threadIdx.x;

    __shared__ float s[3 * 1369 + 64];   // stage2 tile OR stage3 workspace

    if (blockIdx.x < IMGS) {
        // ================= stage 2 =================
        const int img = blockIdx.x;
        float* s2 = s + 3 * 1369;

        const float* srcp = g_pool1 + (size_t)img * 4107;
        for (int i = tid; i < 4107; i += 128) s[i] = srcp[i];

        float w[27];
#pragma unroll
        for (int i = 0; i < 27; i++) w[i] = w2g[i];
        const float bias = b2g[0];
        __syncthreads();

        if (tid < 36) {
            const int pr = tid / 6, pc = tid - 6 * pr;
            float pool = -1e30f;
#pragma unroll
            for (int r = 0; r < 3; r++) {
#pragma unroll
                for (int c = 0; c < 3; c++) {
                    const int R = 3 * pr + r;
                    const int C = 3 * pc + c;
                    float a = bias;
#pragma unroll
                    for (int ci = 0; ci < 3; ci++)
#pragma unroll
                        for (int kh = 0; kh < 3; kh++)
#pragma unroll
                            for (int kw = 0; kw < 3; kw++)
                                a = fmaf(s[ci * 1369 + (2 * R + kh) * 37 + 2 * C + kw],
                                         w[ci * 9 + kh * 3 + kw], a);
                    pool = fmaxf(pool, a);
                }
            }
            s2[tid] = fmaxf(pool, 0.f);
        }
        __syncthreads();

        if (tid < 6) {
            float a = linb[tid];
#pragma unroll
            for (int k = 0; k < 36; k++) a = fmaf(s2[k], linw[tid * 36 + k], a);
            g_nf[img * 6 + tid] = a;
        }
        __threadfence();
        __syncthreads();
        if (tid == 0) atomicAdd(&g_done, 1);
        return;
    }

    // ================= stage 3 =================
    const int n = blockIdx.x - IMGS;
    float* feat = s;          // 240
    float* h1   = s + 240;    // 120
    float* h2   = s + 360;    // 60
    float* red  = s + 420;    // 240 partials (reused)

    const float* posn = pos + n * 120;

    // --- g_nf-independent half of feat + weight L2 warmup (overlaps stage2) ---
    if (tid < 120) {
        const int f  = tid / 24;
        const int nn = (tid / 6) % 4;
        const int d  = tid % 6;
        const float* att = attmap + n * 80 + f * 16;
        float acc = 0.f;
        const float fb = frameb[d];
#pragma unroll
        for (int j = 0; j < 4; j++) {
            float m = fb;
#pragma unroll
            for (int e = 0; e < 6; e++)
                m = fmaf(posn[(f * 4 + j) * 6 + e], framew[d * 6 + e], m);
            acc = fmaf(att[j * 4 + nn], m, acc);
        }
        if (f >= 1) {
            float l = lastb[d];
#pragma unroll
            for (int e = 0; e < 6; e++)
                l = fmaf(posn[((f - 1) * 4 + nn) * 6 + e], lastw[d * 6 + e], l);
            acc += l;
        }
        feat[f * 48 + nn * 12 + 6 + d] = acc;
    }
    // warm fc weights into L2/L1 while stage2 runs (block n==0 only)
    if (n == 0) {
        float acc = 0.f;
        const float4* p1 = (const float4*)fc1w;
        for (int i = tid; i < 7200; i += 128) {
            float4 v = p1[i]; acc += v.x + v.y + v.z + v.w;
        }
        const float4* p2 = (const float4*)fc2w;
        for (int i = tid; i < 1800; i += 128) {
            float4 v = p2[i]; acc += v.x + v.y + v.z + v.w;
        }
        if (acc == -1.2345678e33f) g_sink = acc;
    }

    // --- wait for all stage2 blocks ---
    if (tid == 0) {
        while (atomicAdd(&g_done, 0) < IMGS) { }
    }
    __syncthreads();
    __threadfence();

    if (tid < 120) {
        const int f  = tid / 24;
        const int nn = (tid / 6) % 4;
        const int d  = tid % 6;
        feat[f * 48 + nn * 12 + d] = g_nf[(n * 20 + f * 4 + nn) * 6 + d];
    }
    __syncthreads();

    // fc1: 120 outputs, K=240: each thread one output (full K, 60 float4)
    if (tid < 120) {
        const float4* wr = (const float4*)(fc1w + tid * 240);
        const float4* fe = (const float4*)feat;
        float acc = fc1b[tid];
#pragma unroll
        for (int k = 0; k < 60; k++) {
            float4 w4 = wr[k], f4 = fe[k];
            acc = fmaf(f4.x, w4.x, acc);
            acc = fmaf(f4.y, w4.y, acc);
            acc = fmaf(f4.z, w4.z, acc);
            acc = fmaf(f4.w, w4.w, acc);
        }
        h1[tid] = fmaxf(acc, 0.f);
    }
    __syncthreads();

    // fc2: 60 outputs, split-K over thread pairs (tid, tid+64)
    {
        const int half = tid >> 6;      // 0 or 1
        const int o    = tid & 63;
        if (o < 60 && half < 2) {
            const float4* wr = (const float4*)(fc2w + o * 120 + half * 60);
            const float4* hh = (const float4*)h1 + half * 15;
            float acc = 0.f;
#pragma unroll
            for (int k = 0; k < 15; k++) {
                float4 w4 = wr[k], f4 = hh[k];
                acc = fmaf(f4.x, w4.x, acc);
                acc = fmaf(f4.y, w4.y, acc);
                acc = fmaf(f4.z, w4.z, acc);
                acc = fmaf(f4.w, w4.w, acc);
            }
            red[half * 60 + o] = acc;
        }
    }
    __syncthreads();
    if (tid < 60) h2[tid] = fmaxf(red[tid] + red[60 + tid] + fc2b[tid], 0.f);
    __syncthreads();

    // fc3: 6 outputs
    if (tid < 6) {
        float acc = fc3b[tid];
#pragma unroll
        for (int k = 0; k < 60; k++) acc = fmaf(h2[k], fc3w[tid * 60 + k], acc);
        out[n * 6 + tid] = acc;
    }
}

// ---------------------------------------------------------------------------
extern "C" void kernel_launch(void* const* d_in, const int* in_sizes, int n_in,
                              void* d_out, int out_size)
{
    const float* nodes  = (const float*)d_in[0];
    const float* pos    = (const float*)d_in[1];
    const float* attmap = (const float*)d_in[2];
    // d_in[3] = depths (unused)
    const float* conv1w = (const float*)d_in[4];
    const float* conv1b = (const float*)d_in[5];
    const float* conv2w = (const float*)d_in[6];
    const float* conv2b = (const float*)d_in[7];
    const float* linw   = (const float*)d_in[8];
    const float* linb   = (const float*)d_in[9];
    const float* framew = (const float*)d_in[10];
    const float* frameb = (const float*)d_in[11];
    const float* lastw  = (const float*)d_in[12];
    const float* lastb  = (const float*)d_in[13];
    const float* fc1w   = (const float*)d_in[14];
    const float* fc1b   = (const float*)d_in[15];
    const float* fc2w   = (const float*)d_in[16];
    const float* fc2b   = (const float*)d_in[17];
    const float* fc3w   = (const float*)d_in[18];
    const float* fc3b   = (const float*)d_in[19];

    cudaFuncSetAttribute(stage1_kernel,
                         cudaFuncAttributeMaxDynamicSharedMemorySize, S1_SMEM_BYTES);

    stage1_kernel<<<IMGS, 128, S1_SMEM_BYTES>>>(nodes, conv1w, conv1b);
    stage23_kernel<<<IMGS + 64, 128>>>(conv2w, conv2b, linw, linb,
                                       pos, attmap, framew, frameb,
                                       lastw, lastb, fc1w, fc1b,
                                       fc2w, fc2b, fc3w, fc3b,
                                       (float*)d_out);
}